// round 2
// baseline (speedup 1.0000x reference)
#include <cuda_runtime.h>
#include <cstdint>

#define NB 4
#define NS 2048
#define ND 512
#define NH 8
#define NDH 64

// ---------------- scratch (device globals; no allocations) ----------------
__device__ float g_Q[NB*NH*NDH*NS];      // [b][h][d][s]  (pre-scaled by 1/8)
__device__ float g_K[NB*NH*NDH*NS];      // [b][h][d][s]
__device__ float g_V[(size_t)NB*NH*NS*NDH];      // [b][h][s][d]
__device__ float g_ctx[(size_t)NB*NS*ND];        // [b*s][d]
__device__ float g_biasT[NH*4096];               // [h][delta+2047]
__device__ unsigned g_maskbits[(size_t)NB*NS*NS/32];
__device__ int g_mode;

// ---------------- mask dtype detection ----------------
__global__ void detect_mask_kernel(const void* mask) {
    __shared__ int sF, sI;
    if (threadIdx.x == 0) { sF = 1; sI = 1; }
    __syncthreads();
    unsigned w = ((const unsigned*)mask)[threadIdx.x];
    if (!(w == 0u || w == 0x3F800000u)) sF = 0;
    if (!(w == 0u || w == 1u)) sI = 0;
    __syncthreads();
    if (threadIdx.x == 0) g_mode = sF ? 0 : (sI ? 1 : 2);
}

// ---------------- mask bit-packing ----------------
__global__ void maskprep_kernel(const void* mask) {
    int w = blockIdx.x * blockDim.x + threadIdx.x;   // word index < B*S*S/32
    int mode = g_mode;
    unsigned bits = 0;
    size_t base = (size_t)w * 32;
    if (mode == 0) {
        const float* mf = (const float*)mask;
        #pragma unroll 8
        for (int j = 0; j < 32; j++) bits |= (mf[base + j] != 0.0f ? 1u : 0u) << j;
    } else if (mode == 1) {
        const int* mi = (const int*)mask;
        #pragma unroll 8
        for (int j = 0; j < 32; j++) bits |= (mi[base + j] != 0 ? 1u : 0u) << j;
    } else {
        const unsigned char* mb = (const unsigned char*)mask;
        #pragma unroll 8
        for (int j = 0; j < 32; j++) bits |= (mb[base + j] != 0 ? 1u : 0u) << j;
    }
    g_maskbits[w] = bits;
}

// ---------------- T5 relative-position bias table ----------------
__global__ void biastab_kernel(const float* __restrict__ rel_bias) {
    int t = blockIdx.x * blockDim.x + threadIdx.x;
    if (t >= NH * 4096) return;
    int h = t >> 12;
    int dix = t & 4095;
    int delta = dix - 2047;               // delta = k - q
    int rb = (delta > 0) ? 16 : 0;
    int ad = abs(delta);
    int bucket;
    if (ad < 8) {
        bucket = rb + ad;
    } else {
        float fl = logf((float)ad / 8.0f) / logf(16.0f) * 8.0f;
        int l = (int)fl;                  // truncation, fl >= 0
        int lg = 8 + l; if (lg > 15) lg = 15;
        bucket = rb + lg;
    }
    g_biasT[t] = rel_bias[bucket * NH + h];
}

// ---------------- fused QKV projection GEMM (128x128 tile, 8x8 micro) ----------------
__global__ __launch_bounds__(256) void gemm_qkv_kernel(
    const float* __restrict__ key, const float* __restrict__ value, const float* __restrict__ query,
    const float* __restrict__ Wq, const float* __restrict__ bq,
    const float* __restrict__ Wk, const float* __restrict__ bk,
    const float* __restrict__ Wv, const float* __restrict__ bv)
{
    __shared__ __align__(16) float As[16][132];   // [kk][m]
    __shared__ __align__(16) float Bs[16][128];   // [kk][n]
    const int z = blockIdx.z;
    const float* X    = (z == 0) ? query : (z == 1) ? key : value;
    const float* W    = (z == 0) ? Wq    : (z == 1) ? Wk  : Wv;
    const float* bias = (z == 0) ? bq    : (z == 1) ? bk  : bv;
    float* dst        = (z == 0) ? g_Q   : (z == 1) ? g_K : g_V;

    const int tid = threadIdx.x;
    const int tx = tid & 15, ty = tid >> 4;
    const int m0 = blockIdx.y * 128, n0 = blockIdx.x * 128;

    float acc[8][8];
    #pragma unroll
    for (int i = 0; i < 8; i++)
        #pragma unroll
        for (int j = 0; j < 8; j++) acc[i][j] = 0.0f;

    for (int k0 = 0; k0 < ND; k0 += 16) {
        #pragma unroll
        for (int i = 0; i < 2; i++) {
            int c = tid + i * 256;
            int m = c >> 2;
            int kq = (c & 3) << 2;
            float4 v = *(const float4*)&X[(size_t)(m0 + m) * ND + k0 + kq];
            As[kq + 0][m] = v.x; As[kq + 1][m] = v.y;
            As[kq + 2][m] = v.z; As[kq + 3][m] = v.w;
        }
        #pragma unroll
        for (int i = 0; i < 2; i++) {
            int c = tid + i * 256;
            int kk = c >> 5;
            int nq = (c & 31) << 2;
            *(float4*)&Bs[kk][nq] = *(const float4*)&W[(size_t)(k0 + kk) * ND + n0 + nq];
        }
        __syncthreads();
        #pragma unroll
        for (int kk = 0; kk < 16; kk++) {
            float a[8], bb[8];
            *(float4*)&a[0] = *(float4*)&As[kk][4 * ty];
            *(float4*)&a[4] = *(float4*)&As[kk][64 + 4 * ty];
            *(float4*)&bb[0] = *(float4*)&Bs[kk][4 * tx];
            *(float4*)&bb[4] = *(float4*)&Bs[kk][64 + 4 * tx];
            #pragma unroll
            for (int i = 0; i < 8; i++)
                #pragma unroll
                for (int j = 0; j < 8; j++)
                    acc[i][j] += a[i] * bb[j];
        }
        __syncthreads();
    }

    #pragma unroll
    for (int i = 0; i < 8; i++) {
        int m = m0 + ((i < 4) ? (4 * ty + i) : (64 + 4 * ty + i - 4));
        int b = m >> 11, s = m & 2047;
        #pragma unroll
        for (int j = 0; j < 8; j++) {
            int n = n0 + ((j < 4) ? (4 * tx + j) : (64 + 4 * tx + j - 4));
            float v = acc[i][j] + bias[n];
            int h = n >> 6, dh = n & 63;
            if (z == 0) {
                v *= 0.125f;                                   // 1/sqrt(64)
                dst[((size_t)(b * NH + h) * NDH + dh) * NS + s] = v;   // [b][h][d][s]
            } else if (z == 1) {
                dst[((size_t)(b * NH + h) * NDH + dh) * NS + s] = v;
            } else {
                dst[((size_t)(b * NH + h) * NS + s) * NDH + dh] = v;   // [b][h][s][d]
            }
        }
    }
}

// ---------------- flash attention (fp32, 64x64 tiles) ----------------
__global__ __launch_bounds__(256) void attn_kernel() {
    extern __shared__ __align__(16) float sm[];
    float* Qs = sm;            // [d][q] 64x64
    float* Ks = sm + 4096;     // [d][k]
    float* Vs = sm + 8192;     // [k][d]
    float* Ps = sm + 12288;    // [k][q] swizzled

    const int b = blockIdx.z, h = blockIdx.y;
    const int q0 = blockIdx.x * 64;
    const int tid = threadIdx.x;
    const int tx = tid & 15, ty = tid >> 4;

    const float* Qg = g_Q + (size_t)((b * NH + h) * NDH) * NS;
    const float* Kg = g_K + (size_t)((b * NH + h) * NDH) * NS;
    const float* Vg = g_V + (size_t)((b * NH + h) * NS) * NDH;
    const unsigned* Mg = g_maskbits + (size_t)b * NS * (NS / 32);
    const float* Bt = g_biasT + (h << 12);

    #pragma unroll
    for (int i = 0; i < 4; i++) {
        int c = tid + i * 256;
        int d = c >> 4;
        int q4 = (c & 15) << 2;
        *(float4*)&Qs[d * 64 + q4] = *(const float4*)&Qg[(size_t)d * NS + q0 + q4];
    }

    float mrow[4], lrow[4], O[4][4];
    #pragma unroll
    for (int ry = 0; ry < 4; ry++) {
        mrow[ry] = -1e30f; lrow[ry] = 0.0f;
        #pragma unroll
        for (int cx = 0; cx < 4; cx++) O[ry][cx] = 0.0f;
    }

    for (int k0 = 0; k0 < NS; k0 += 64) {
        #pragma unroll
        for (int i = 0; i < 4; i++) {
            int c = tid + i * 256;
            int d = c >> 4;
            int x4 = (c & 15) << 2;
            *(float4*)&Ks[d * 64 + x4] = *(const float4*)&Kg[(size_t)d * NS + k0 + x4];
            *(float4*)&Vs[d * 64 + x4] = *(const float4*)&Vg[(size_t)(k0 + d) * NDH + x4];
        }
        __syncthreads();

        float sacc[4][4];
        #pragma unroll
        for (int i = 0; i < 4; i++)
            #pragma unroll
            for (int j = 0; j < 4; j++) sacc[i][j] = 0.0f;

        #pragma unroll 16
        for (int d = 0; d < 64; d++) {
            float ar[4], br[4];
            *(float4*)ar = *(float4*)&Qs[d * 64 + 4 * ty];
            *(float4*)br = *(float4*)&Ks[d * 64 + 4 * tx];
            #pragma unroll
            for (int i = 0; i < 4; i++)
                #pragma unroll
                for (int j = 0; j < 4; j++)
                    sacc[i][j] += ar[i] * br[j];
        }

        #pragma unroll
        for (int ry = 0; ry < 4; ry++) {
            int q = q0 + 4 * ty + ry;
            unsigned w = Mg[(size_t)q * (NS / 32) + (k0 >> 5) + (tx >> 3)];
            #pragma unroll
            for (int cx = 0; cx < 4; cx++) {
                int kk = 4 * tx + cx;
                float v = sacc[ry][cx] + Bt[(k0 + kk) - q + 2047];
                if ((w >> (kk & 31)) & 1u) v = -1e18f;
                sacc[ry][cx] = v;
            }
            float rmax = fmaxf(fmaxf(sacc[ry][0], sacc[ry][1]), fmaxf(sacc[ry][2], sacc[ry][3]));
            rmax = fmaxf(rmax, __shfl_xor_sync(0xffffffffu, rmax, 1));
            rmax = fmaxf(rmax, __shfl_xor_sync(0xffffffffu, rmax, 2));
            rmax = fmaxf(rmax, __shfl_xor_sync(0xffffffffu, rmax, 4));
            rmax = fmaxf(rmax, __shfl_xor_sync(0xffffffffu, rmax, 8));
            float mnew = fmaxf(mrow[ry], rmax);
            float alpha = __expf(mrow[ry] - mnew);
            mrow[ry] = mnew;
            float rsum = 0.0f;
            #pragma unroll
            for (int cx = 0; cx < 4; cx++) {
                float p = __expf(sacc[ry][cx] - mnew);
                sacc[ry][cx] = p;
                rsum += p;
            }
            rsum += __shfl_xor_sync(0xffffffffu, rsum, 1);
            rsum += __shfl_xor_sync(0xffffffffu, rsum, 2);
            rsum += __shfl_xor_sync(0xffffffffu, rsum, 4);
            rsum += __shfl_xor_sync(0xffffffffu, rsum, 8);
            lrow[ry] = lrow[ry] * alpha + rsum;
            #pragma unroll
            for (int cx = 0; cx < 4; cx++) O[ry][cx] *= alpha;
        }

        // store P transposed [k][q] with XOR swizzle on the q float4-group
        #pragma unroll
        for (int cx = 0; cx < 4; cx++) {
            int kk = 4 * tx + cx;
            int cg = ty ^ ((kk + (kk >> 4)) & 15);
            float4 pv = make_float4(sacc[0][cx], sacc[1][cx], sacc[2][cx], sacc[3][cx]);
            *(float4*)&Ps[kk * 64 + cg * 4] = pv;
        }
        __syncthreads();

        #pragma unroll 16
        for (int kk = 0; kk < 64; kk++) {
            int cg = ty ^ ((kk + (kk >> 4)) & 15);
            float ar[4], vr[4];
            *(float4*)ar = *(float4*)&Ps[kk * 64 + cg * 4];
            *(float4*)vr = *(float4*)&Vs[kk * 64 + 4 * tx];
            #pragma unroll
            for (int i = 0; i < 4; i++)
                #pragma unroll
                for (int j = 0; j < 4; j++)
                    O[i][j] += ar[i] * vr[j];
        }
        __syncthreads();
    }

    #pragma unroll
    for (int ry = 0; ry < 4; ry++) {
        float inv = 1.0f / lrow[ry];
        int q = q0 + 4 * ty + ry;
        float4 o = make_float4(O[ry][0] * inv, O[ry][1] * inv, O[ry][2] * inv, O[ry][3] * inv);
        *(float4*)&g_ctx[((size_t)(b * NS + q)) * ND + h * NDH + 4 * tx] = o;
    }
}

// ---------------- output projection GEMM ----------------
__global__ __launch_bounds__(256) void gemm_out_kernel(
    const float* __restrict__ Wo, const float* __restrict__ bo, float* __restrict__ out)
{
    __shared__ __align__(16) float As[16][132];
    __shared__ __align__(16) float Bs[16][128];
    const int tid = threadIdx.x;
    const int tx = tid & 15, ty = tid >> 4;
    const int m0 = blockIdx.y * 128, n0 = blockIdx.x * 128;

    float acc[8][8];
    #pragma unroll
    for (int i = 0; i < 8; i++)
        #pragma unroll
        for (int j = 0; j < 8; j++) acc[i][j] = 0.0f;

    for (int k0 = 0; k0 < ND; k0 += 16) {
        #pragma unroll
        for (int i = 0; i < 2; i++) {
            int c = tid + i * 256;
            int m = c >> 2;
            int kq = (c & 3) << 2;
            float4 v = *(const float4*)&g_ctx[(size_t)(m0 + m) * ND + k0 + kq];
            As[kq + 0][m] = v.x; As[kq + 1][m] = v.y;
            As[kq + 2][m] = v.z; As[kq + 3][m] = v.w;
        }
        #pragma unroll
        for (int i = 0; i < 2; i++) {
            int c = tid + i * 256;
            int kk = c >> 5;
            int nq = (c & 31) << 2;
            *(float4*)&Bs[kk][nq] = *(const float4*)&Wo[(size_t)(k0 + kk) * ND + n0 + nq];
        }
        __syncthreads();
        #pragma unroll
        for (int kk = 0; kk < 16; kk++) {
            float a[8], bb[8];
            *(float4*)&a[0] = *(float4*)&As[kk][4 * ty];
            *(float4*)&a[4] = *(float4*)&As[kk][64 + 4 * ty];
            *(float4*)&bb[0] = *(float4*)&Bs[kk][4 * tx];
            *(float4*)&bb[4] = *(float4*)&Bs[kk][64 + 4 * tx];
            #pragma unroll
            for (int i = 0; i < 8; i++)
                #pragma unroll
                for (int j = 0; j < 8; j++)
                    acc[i][j] += a[i] * bb[j];
        }
        __syncthreads();
    }

    #pragma unroll
    for (int i = 0; i < 8; i++) {
        int m = m0 + ((i < 4) ? (4 * ty + i) : (64 + 4 * ty + i - 4));
        #pragma unroll
        for (int jh = 0; jh < 2; jh++) {
            int n = n0 + jh * 64 + 4 * tx;
            float4 v = make_float4(acc[i][jh * 4 + 0] + bo[n + 0],
                                   acc[i][jh * 4 + 1] + bo[n + 1],
                                   acc[i][jh * 4 + 2] + bo[n + 2],
                                   acc[i][jh * 4 + 3] + bo[n + 3]);
            *(float4*)&out[(size_t)m * ND + n] = v;
        }
    }
}

// ---------------- launch ----------------
extern "C" void kernel_launch(void* const* d_in, const int* in_sizes, int n_in,
                              void* d_out, int out_size) {
    const float* key      = (const float*)d_in[0];
    const float* value    = (const float*)d_in[1];
    const float* query    = (const float*)d_in[2];
    const float* Wq       = (const float*)d_in[3];
    const float* bq       = (const float*)d_in[4];
    const float* Wk       = (const float*)d_in[5];
    const float* bk       = (const float*)d_in[6];
    const float* Wv       = (const float*)d_in[7];
    const float* bv       = (const float*)d_in[8];
    const float* Wo       = (const float*)d_in[9];
    const float* bo       = (const float*)d_in[10];
    const float* rel_bias = (const float*)d_in[11];
    const void*  mask     = (const void*)d_in[12];
    float* out = (float*)d_out;

    cudaFuncSetAttribute(attn_kernel, cudaFuncAttributeMaxDynamicSharedMemorySize, 65536);

    detect_mask_kernel<<<1, 1024>>>(mask);
    maskprep_kernel<<<(NB * NS * NS / 32) / 256, 256>>>(mask);
    biastab_kernel<<<(NH * 4096) / 256, 256>>>(rel_bias);

    dim3 pgrid(ND / 128, (NB * NS) / 128, 3);
    gemm_qkv_kernel<<<pgrid, 256>>>(key, value, query, Wq, bq, Wk, bk, Wv, bv);

    dim3 agrid(NS / 64, NH, NB);
    attn_kernel<<<agrid, 256, 65536>>>();

    dim3 ogrid(ND / 128, (NB * NS) / 128);
    gemm_out_kernel<<<ogrid, 256>>>(Wo, bo, out);
}

// round 3
// speedup vs baseline: 1.0008x; 1.0008x over previous
#include <cuda_runtime.h>
#include <cstdint>

#define NB 4
#define NS 2048
#define ND 512
#define NH 8
#define NDH 64

// ---------------- scratch (device globals; no allocations) ----------------
__device__ float g_Q[NB*NH*NDH*NS];      // [b][h][d][s]  (pre-scaled by 1/8)
__device__ float g_K[NB*NH*NDH*NS];      // [b][h][d][s]
__device__ float g_V[(size_t)NB*NH*NS*NDH];      // [b][h][s][d]
__device__ float g_ctx[(size_t)NB*NS*ND];        // [b*s][d]
__device__ float g_biasT[NH*4096];               // [h][delta+2047]
__device__ unsigned g_maskbits[(size_t)NB*NS*NS/32];
__device__ int g_mode;

// ---------------- mask dtype detection ----------------
__global__ void detect_mask_kernel(const void* mask) {
    __shared__ int sF, sI;
    if (threadIdx.x == 0) { sF = 1; sI = 1; }
    __syncthreads();
    unsigned w = ((const unsigned*)mask)[threadIdx.x];
    if (!(w == 0u || w == 0x3F800000u)) sF = 0;
    if (!(w == 0u || w == 1u)) sI = 0;
    __syncthreads();
    if (threadIdx.x == 0) g_mode = sF ? 0 : (sI ? 1 : 2);
}

// ---------------- mask bit-packing ----------------
__global__ void maskprep_kernel(const void* mask) {
    int w = blockIdx.x * blockDim.x + threadIdx.x;   // word index < B*S*S/32
    int mode = g_mode;
    unsigned bits = 0;
    size_t base = (size_t)w * 32;
    if (mode == 0) {
        const float* mf = (const float*)mask;
        #pragma unroll 8
        for (int j = 0; j < 32; j++) bits |= (mf[base + j] != 0.0f ? 1u : 0u) << j;
    } else if (mode == 1) {
        const int* mi = (const int*)mask;
        #pragma unroll 8
        for (int j = 0; j < 32; j++) bits |= (mi[base + j] != 0 ? 1u : 0u) << j;
    } else {
        const unsigned char* mb = (const unsigned char*)mask;
        #pragma unroll 8
        for (int j = 0; j < 32; j++) bits |= (mb[base + j] != 0 ? 1u : 0u) << j;
    }
    g_maskbits[w] = bits;
}

// ---------------- T5 relative-position bias table ----------------
__global__ void biastab_kernel(const float* __restrict__ rel_bias) {
    int t = blockIdx.x * blockDim.x + threadIdx.x;
    if (t >= NH * 4096) return;
    int h = t >> 12;
    int dix = t & 4095;
    int delta = dix - 2047;               // delta = k - q
    int rb = (delta > 0) ? 16 : 0;
    int ad = abs(delta);
    int bucket;
    if (ad < 8) {
        bucket = rb + ad;
    } else {
        float fl = logf((float)ad / 8.0f) / logf(16.0f) * 8.0f;
        int l = (int)fl;                  // truncation, fl >= 0
        int lg = 8 + l; if (lg > 15) lg = 15;
        bucket = rb + lg;
    }
    g_biasT[t] = rel_bias[bucket * NH + h];
}

// ---------------- fused QKV projection GEMM (128x128 tile, 8x8 micro) ----------------
__global__ __launch_bounds__(256) void gemm_qkv_kernel(
    const float* __restrict__ key, const float* __restrict__ value, const float* __restrict__ query,
    const float* __restrict__ Wq, const float* __restrict__ bq,
    const float* __restrict__ Wk, const float* __restrict__ bk,
    const float* __restrict__ Wv, const float* __restrict__ bv)
{
    __shared__ __align__(16) float As[16][132];   // [kk][m]
    __shared__ __align__(16) float Bs[16][128];   // [kk][n]
    const int z = blockIdx.z;
    const float* X    = (z == 0) ? query : (z == 1) ? key : value;
    const float* W    = (z == 0) ? Wq    : (z == 1) ? Wk  : Wv;
    const float* bias = (z == 0) ? bq    : (z == 1) ? bk  : bv;
    float* dst        = (z == 0) ? g_Q   : (z == 1) ? g_K : g_V;

    const int tid = threadIdx.x;
    const int tx = tid & 15, ty = tid >> 4;
    const int m0 = blockIdx.y * 128, n0 = blockIdx.x * 128;

    float acc[8][8];
    #pragma unroll
    for (int i = 0; i < 8; i++)
        #pragma unroll
        for (int j = 0; j < 8; j++) acc[i][j] = 0.0f;

    for (int k0 = 0; k0 < ND; k0 += 16) {
        #pragma unroll
        for (int i = 0; i < 2; i++) {
            int c = tid + i * 256;
            int m = c >> 2;
            int kq = (c & 3) << 2;
            float4 v = *(const float4*)&X[(size_t)(m0 + m) * ND + k0 + kq];
            As[kq + 0][m] = v.x; As[kq + 1][m] = v.y;
            As[kq + 2][m] = v.z; As[kq + 3][m] = v.w;
        }
        #pragma unroll
        for (int i = 0; i < 2; i++) {
            int c = tid + i * 256;
            int kk = c >> 5;
            int nq = (c & 31) << 2;
            *(float4*)&Bs[kk][nq] = *(const float4*)&W[(size_t)(k0 + kk) * ND + n0 + nq];
        }
        __syncthreads();
        #pragma unroll
        for (int kk = 0; kk < 16; kk++) {
            float a[8], bb[8];
            *(float4*)&a[0] = *(float4*)&As[kk][4 * ty];
            *(float4*)&a[4] = *(float4*)&As[kk][64 + 4 * ty];
            *(float4*)&bb[0] = *(float4*)&Bs[kk][4 * tx];
            *(float4*)&bb[4] = *(float4*)&Bs[kk][64 + 4 * tx];
            #pragma unroll
            for (int i = 0; i < 8; i++)
                #pragma unroll
                for (int j = 0; j < 8; j++)
                    acc[i][j] += a[i] * bb[j];
        }
        __syncthreads();
    }

    #pragma unroll
    for (int i = 0; i < 8; i++) {
        int m = m0 + ((i < 4) ? (4 * ty + i) : (64 + 4 * ty + i - 4));
        int b = m >> 11, s = m & 2047;
        #pragma unroll
        for (int j = 0; j < 8; j++) {
            int n = n0 + ((j < 4) ? (4 * tx + j) : (64 + 4 * tx + j - 4));
            float v = acc[i][j] + bias[n];
            int h = n >> 6, dh = n & 63;
            if (z == 0) {
                v *= 0.125f;                                   // 1/sqrt(64)
                dst[((size_t)(b * NH + h) * NDH + dh) * NS + s] = v;   // [b][h][d][s]
            } else if (z == 1) {
                dst[((size_t)(b * NH + h) * NDH + dh) * NS + s] = v;
            } else {
                dst[((size_t)(b * NH + h) * NS + s) * NDH + dh] = v;   // [b][h][s][d]
            }
        }
    }
}

// ---------------- flash attention (fp32, 64x64 tiles) ----------------
__global__ __launch_bounds__(256) void attn_kernel() {
    extern __shared__ __align__(16) float sm[];
    float* Qs = sm;            // [d][q] 64x64
    float* Ks = sm + 4096;     // [d][k]
    float* Vs = sm + 8192;     // [k][d]
    float* Ps = sm + 12288;    // [k][q] swizzled

    const int b = blockIdx.z, h = blockIdx.y;
    const int q0 = blockIdx.x * 64;
    const int tid = threadIdx.x;
    const int tx = tid & 15, ty = tid >> 4;

    const float* Qg = g_Q + (size_t)((b * NH + h) * NDH) * NS;
    const float* Kg = g_K + (size_t)((b * NH + h) * NDH) * NS;
    const float* Vg = g_V + (size_t)((b * NH + h) * NS) * NDH;
    const unsigned* Mg = g_maskbits + (size_t)b * NS * (NS / 32);
    const float* Bt = g_biasT + (h << 12);

    #pragma unroll
    for (int i = 0; i < 4; i++) {
        int c = tid + i * 256;
        int d = c >> 4;
        int q4 = (c & 15) << 2;
        *(float4*)&Qs[d * 64 + q4] = *(const float4*)&Qg[(size_t)d * NS + q0 + q4];
    }

    float mrow[4], lrow[4], O[4][4];
    #pragma unroll
    for (int ry = 0; ry < 4; ry++) {
        mrow[ry] = -1e30f; lrow[ry] = 0.0f;
        #pragma unroll
        for (int cx = 0; cx < 4; cx++) O[ry][cx] = 0.0f;
    }

    for (int k0 = 0; k0 < NS; k0 += 64) {
        #pragma unroll
        for (int i = 0; i < 4; i++) {
            int c = tid + i * 256;
            int d = c >> 4;
            int x4 = (c & 15) << 2;
            *(float4*)&Ks[d * 64 + x4] = *(const float4*)&Kg[(size_t)d * NS + k0 + x4];
            *(float4*)&Vs[d * 64 + x4] = *(const float4*)&Vg[(size_t)(k0 + d) * NDH + x4];
        }
        __syncthreads();

        float sacc[4][4];
        #pragma unroll
        for (int i = 0; i < 4; i++)
            #pragma unroll
            for (int j = 0; j < 4; j++) sacc[i][j] = 0.0f;

        #pragma unroll 16
        for (int d = 0; d < 64; d++) {
            float ar[4], br[4];
            *(float4*)ar = *(float4*)&Qs[d * 64 + 4 * ty];
            *(float4*)br = *(float4*)&Ks[d * 64 + 4 * tx];
            #pragma unroll
            for (int i = 0; i < 4; i++)
                #pragma unroll
                for (int j = 0; j < 4; j++)
                    sacc[i][j] += ar[i] * br[j];
        }

        #pragma unroll
        for (int ry = 0; ry < 4; ry++) {
            int q = q0 + 4 * ty + ry;
            unsigned w = Mg[(size_t)q * (NS / 32) + (k0 >> 5) + (tx >> 3)];
            #pragma unroll
            for (int cx = 0; cx < 4; cx++) {
                int kk = 4 * tx + cx;
                float v = sacc[ry][cx] + Bt[(k0 + kk) - q + 2047];
                if ((w >> (kk & 31)) & 1u) v = -1e18f;
                sacc[ry][cx] = v;
            }
            float rmax = fmaxf(fmaxf(sacc[ry][0], sacc[ry][1]), fmaxf(sacc[ry][2], sacc[ry][3]));
            rmax = fmaxf(rmax, __shfl_xor_sync(0xffffffffu, rmax, 1));
            rmax = fmaxf(rmax, __shfl_xor_sync(0xffffffffu, rmax, 2));
            rmax = fmaxf(rmax, __shfl_xor_sync(0xffffffffu, rmax, 4));
            rmax = fmaxf(rmax, __shfl_xor_sync(0xffffffffu, rmax, 8));
            float mnew = fmaxf(mrow[ry], rmax);
            float alpha = __expf(mrow[ry] - mnew);
            mrow[ry] = mnew;
            float rsum = 0.0f;
            #pragma unroll
            for (int cx = 0; cx < 4; cx++) {
                float p = __expf(sacc[ry][cx] - mnew);
                sacc[ry][cx] = p;
                rsum += p;
            }
            rsum += __shfl_xor_sync(0xffffffffu, rsum, 1);
            rsum += __shfl_xor_sync(0xffffffffu, rsum, 2);
            rsum += __shfl_xor_sync(0xffffffffu, rsum, 4);
            rsum += __shfl_xor_sync(0xffffffffu, rsum, 8);
            lrow[ry] = lrow[ry] * alpha + rsum;
            #pragma unroll
            for (int cx = 0; cx < 4; cx++) O[ry][cx] *= alpha;
        }

        // store P transposed [k][q] with XOR swizzle on the q float4-group
        #pragma unroll
        for (int cx = 0; cx < 4; cx++) {
            int kk = 4 * tx + cx;
            int cg = ty ^ ((kk + (kk >> 4)) & 15);
            float4 pv = make_float4(sacc[0][cx], sacc[1][cx], sacc[2][cx], sacc[3][cx]);
            *(float4*)&Ps[kk * 64 + cg * 4] = pv;
        }
        __syncthreads();

        #pragma unroll 16
        for (int kk = 0; kk < 64; kk++) {
            int cg = ty ^ ((kk + (kk >> 4)) & 15);
            float ar[4], vr[4];
            *(float4*)ar = *(float4*)&Ps[kk * 64 + cg * 4];
            *(float4*)vr = *(float4*)&Vs[kk * 64 + 4 * tx];
            #pragma unroll
            for (int i = 0; i < 4; i++)
                #pragma unroll
                for (int j = 0; j < 4; j++)
                    O[i][j] += ar[i] * vr[j];
        }
        __syncthreads();
    }

    #pragma unroll
    for (int ry = 0; ry < 4; ry++) {
        float inv = 1.0f / lrow[ry];
        int q = q0 + 4 * ty + ry;
        float4 o = make_float4(O[ry][0] * inv, O[ry][1] * inv, O[ry][2] * inv, O[ry][3] * inv);
        *(float4*)&g_ctx[((size_t)(b * NS + q)) * ND + h * NDH + 4 * tx] = o;
    }
}

// ---------------- output projection GEMM ----------------
__global__ __launch_bounds__(256) void gemm_out_kernel(
    const float* __restrict__ Wo, const float* __restrict__ bo, float* __restrict__ out)
{
    __shared__ __align__(16) float As[16][132];
    __shared__ __align__(16) float Bs[16][128];
    const int tid = threadIdx.x;
    const int tx = tid & 15, ty = tid >> 4;
    const int m0 = blockIdx.y * 128, n0 = blockIdx.x * 128;

    float acc[8][8];
    #pragma unroll
    for (int i = 0; i < 8; i++)
        #pragma unroll
        for (int j = 0; j < 8; j++) acc[i][j] = 0.0f;

    for (int k0 = 0; k0 < ND; k0 += 16) {
        #pragma unroll
        for (int i = 0; i < 2; i++) {
            int c = tid + i * 256;
            int m = c >> 2;
            int kq = (c & 3) << 2;
            float4 v = *(const float4*)&g_ctx[(size_t)(m0 + m) * ND + k0 + kq];
            As[kq + 0][m] = v.x; As[kq + 1][m] = v.y;
            As[kq + 2][m] = v.z; As[kq + 3][m] = v.w;
        }
        #pragma unroll
        for (int i = 0; i < 2; i++) {
            int c = tid + i * 256;
            int kk = c >> 5;
            int nq = (c & 31) << 2;
            *(float4*)&Bs[kk][nq] = *(const float4*)&Wo[(size_t)(k0 + kk) * ND + n0 + nq];
        }
        __syncthreads();
        #pragma unroll
        for (int kk = 0; kk < 16; kk++) {
            float a[8], bb[8];
            *(float4*)&a[0] = *(float4*)&As[kk][4 * ty];
            *(float4*)&a[4] = *(float4*)&As[kk][64 + 4 * ty];
            *(float4*)&bb[0] = *(float4*)&Bs[kk][4 * tx];
            *(float4*)&bb[4] = *(float4*)&Bs[kk][64 + 4 * tx];
            #pragma unroll
            for (int i = 0; i < 8; i++)
                #pragma unroll
                for (int j = 0; j < 8; j++)
                    acc[i][j] += a[i] * bb[j];
        }
        __syncthreads();
    }

    #pragma unroll
    for (int i = 0; i < 8; i++) {
        int m = m0 + ((i < 4) ? (4 * ty + i) : (64 + 4 * ty + i - 4));
        #pragma unroll
        for (int jh = 0; jh < 2; jh++) {
            int n = n0 + jh * 64 + 4 * tx;
            float4 v = make_float4(acc[i][jh * 4 + 0] + bo[n + 0],
                                   acc[i][jh * 4 + 1] + bo[n + 1],
                                   acc[i][jh * 4 + 2] + bo[n + 2],
                                   acc[i][jh * 4 + 3] + bo[n + 3]);
            *(float4*)&out[(size_t)m * ND + n] = v;
        }
    }
}

// ---------------- launch ----------------
extern "C" void kernel_launch(void* const* d_in, const int* in_sizes, int n_in,
                              void* d_out, int out_size) {
    const float* key      = (const float*)d_in[0];
    const float* value    = (const float*)d_in[1];
    const float* query    = (const float*)d_in[2];
    const float* Wq       = (const float*)d_in[3];
    const float* bq       = (const float*)d_in[4];
    const float* Wk       = (const float*)d_in[5];
    const float* bk       = (const float*)d_in[6];
    const float* Wv       = (const float*)d_in[7];
    const float* bv       = (const float*)d_in[8];
    const float* Wo       = (const float*)d_in[9];
    const float* bo       = (const float*)d_in[10];
    const float* rel_bias = (const float*)d_in[11];
    const void*  mask     = (const void*)d_in[12];
    float* out = (float*)d_out;

    cudaFuncSetAttribute(attn_kernel, cudaFuncAttributeMaxDynamicSharedMemorySize, 65536);

    detect_mask_kernel<<<1, 1024>>>(mask);
    maskprep_kernel<<<(NB * NS * NS / 32) / 256, 256>>>(mask);
    biastab_kernel<<<(NH * 4096) / 256, 256>>>(rel_bias);

    dim3 pgrid(ND / 128, (NB * NS) / 128, 3);
    gemm_qkv_kernel<<<pgrid, 256>>>(key, value, query, Wq, bq, Wk, bk, Wv, bv);

    dim3 agrid(NS / 64, NH, NB);
    attn_kernel<<<agrid, 256, 65536>>>();

    dim3 ogrid(ND / 128, (NB * NS) / 128);
    gemm_out_kernel<<<ogrid, 256>>>(Wo, bo, out);
}

// round 7
// speedup vs baseline: 1.7823x; 1.7808x over previous
#include <cuda_runtime.h>
#include <cuda_bf16.h>
#include <cstdint>

#define NB 4
#define NS 2048
#define ND 512
#define NH 8
#define NDH 64

// ---------------- scratch (device globals; no allocations) ----------------
__device__ __nv_bfloat16 g_Qhi[(size_t)NB*NH*NS*NDH];   // [bh][s][dh]
__device__ __nv_bfloat16 g_Qlo[(size_t)NB*NH*NS*NDH];
__device__ __nv_bfloat16 g_Khi[(size_t)NB*NH*NS*NDH];   // [bh][s][dh]
__device__ __nv_bfloat16 g_Klo[(size_t)NB*NH*NS*NDH];
__device__ __nv_bfloat16 g_Vhi[(size_t)NB*NH*NDH*NS];   // [bh][dh][s]
__device__ __nv_bfloat16 g_Vlo[(size_t)NB*NH*NDH*NS];
__device__ float g_ctx[(size_t)NB*NS*ND];               // [b*s][d] fp32
__device__ float g_biasT[NH*4096];                      // [h][delta+2047]
__device__ unsigned g_maskbits[(size_t)NB*NS*NS/32];
__device__ int g_mode;

// ================= helpers =================
__device__ __forceinline__ uint32_t smem_u32(const void* p) {
    uint32_t a;
    asm("{ .reg .u64 t; cvta.to.shared.u64 t, %1; cvt.u32.u64 %0, t; }" : "=r"(a) : "l"(p));
    return a;
}

#define SWZ128(x) ((x) ^ (((x) >> 3) & 0x70))

__device__ __forceinline__ void ldm_x4(uint32_t (&r)[4], uint32_t addr) {
    asm volatile("ldmatrix.sync.aligned.m8n8.x4.shared.b16 {%0,%1,%2,%3}, [%4];"
        : "=r"(r[0]), "=r"(r[1]), "=r"(r[2]), "=r"(r[3]) : "r"(addr));
}

__device__ __forceinline__ void mma_bf16(float (&c)[4], const uint32_t (&a)[4],
                                         uint32_t b0, uint32_t b1) {
    asm volatile("mma.sync.aligned.m16n8k16.row.col.f32.bf16.bf16.f32 "
        "{%0,%1,%2,%3}, {%4,%5,%6,%7}, {%8,%9}, {%0,%1,%2,%3};"
        : "+f"(c[0]), "+f"(c[1]), "+f"(c[2]), "+f"(c[3])
        : "r"(a[0]), "r"(a[1]), "r"(a[2]), "r"(a[3]), "r"(b0), "r"(b1));
}

__device__ __forceinline__ uint32_t pack_bf16x2(float lo, float hi) {
    uint32_t d;
    asm("cvt.rn.bf16x2.f32 %0, %1, %2;" : "=r"(d) : "f"(hi), "f"(lo));
    return d;
}

// split a float pair into bf16 hi pack and bf16 lo-residual pack
__device__ __forceinline__ void split_pack(float a, float b, uint32_t& hi, uint32_t& lo) {
    __nv_bfloat16 ha = __float2bfloat16_rn(a);
    __nv_bfloat16 hb = __float2bfloat16_rn(b);
    hi = pack_bf16x2(__bfloat16_as_ushort(ha) | 0u, 0u);  // placeholder, replaced below
    // build directly from raw halves to avoid double rounding:
    uint32_t hraw = (uint32_t)__bfloat16_as_ushort(ha) | ((uint32_t)__bfloat16_as_ushort(hb) << 16);
    hi = hraw;
    lo = pack_bf16x2(a - __bfloat162float(ha), b - __bfloat162float(hb));
}

// ================= projection GEMM core (mma.sync, 3-pass bf16x2) =================
// X [M][512] fp32, W [512][N-tiled] fp32 -> acc[16][4] (warp tile m64n32)
#define PJ_AHI 0
#define PJ_ALO 16384
#define PJ_BHI 32768
#define PJ_BLO 49152
#define PJ_TOTAL 65536

__device__ __forceinline__ void mma_gemm_core(
    const float* __restrict__ X, const float* __restrict__ W,
    char* sm, uint32_t sb, int m0, int n0, float (&acc)[16][4])
{
    const int tid = threadIdx.x;
    const int lane = tid & 31, wid = tid >> 5;
    const int wm = wid >> 2, wn = wid & 3;
    const int mat = lane >> 3;
    const int frow = (mat & 1) * 8 + (lane & 7);
    const int fpart = (mat >> 1) * 16;

    for (int c8 = 0; c8 < 8; c8++) {
        const int k0 = c8 * 64;
        // A tile: 128 rows x 64 k, hi/lo split
        #pragma unroll 4
        for (int i = 0; i < 16; i++) {
            int f = tid + i * 256;
            int row = f >> 5, c2 = f & 31;
            float2 v = *(const float2*)&X[(size_t)(m0 + row) * ND + k0 + c2 * 2];
            __nv_bfloat162 hi = __float22bfloat162_rn(v);
            float2 lo2 = make_float2(v.x - __bfloat162float(hi.x),
                                     v.y - __bfloat162float(hi.y));
            __nv_bfloat162 lo = __float22bfloat162_rn(lo2);
            uint32_t off = SWZ128((uint32_t)(row * 128 + c2 * 4));
            *(__nv_bfloat162*)(sm + PJ_AHI + off) = hi;
            *(__nv_bfloat162*)(sm + PJ_ALO + off) = lo;
        }
        // B tile: [n][k] transposed from W[k][n]
        #pragma unroll 4
        for (int i = 0; i < 16; i++) {
            int f = tid + i * 256;
            int n = f & 127, k2 = f >> 7;
            const float* wp = &W[(size_t)(k0 + k2 * 2) * ND + n0 + n];
            float x0 = wp[0], x1 = wp[ND];
            __nv_bfloat162 hi = __floats2bfloat162_rn(x0, x1);
            __nv_bfloat162 lo = __floats2bfloat162_rn(x0 - __bfloat162float(hi.x),
                                                      x1 - __bfloat162float(hi.y));
            uint32_t off = SWZ128((uint32_t)(n * 128 + k2 * 4));
            *(__nv_bfloat162*)(sm + PJ_BHI + off) = hi;
            *(__nv_bfloat162*)(sm + PJ_BLO + off) = lo;
        }
        __syncthreads();

        #pragma unroll
        for (int ks = 0; ks < 4; ks++) {
            const uint32_t off = (uint32_t)(ks * 32 + fpart);
            uint32_t Ahi[4][4], Alo[4][4], Bf[4][2];
            #pragma unroll
            for (int mi = 0; mi < 4; mi++) {
                int row = wm * 64 + mi * 16 + frow;
                uint32_t ad = (uint32_t)(row * 128) + (off ^ ((row << 4) & 0x70));
                ldm_x4(Ahi[mi], sb + PJ_AHI + ad);
            }
            #pragma unroll
            for (int nf = 0; nf < 2; nf++) {
                uint32_t r[4];
                int row = wn * 32 + nf * 16 + frow;
                uint32_t ad = (uint32_t)(row * 128) + (off ^ ((row << 4) & 0x70));
                ldm_x4(r, sb + PJ_BHI + ad);
                Bf[nf*2][0] = r[0]; Bf[nf*2][1] = r[2];
                Bf[nf*2+1][0] = r[1]; Bf[nf*2+1][1] = r[3];
            }
            #pragma unroll
            for (int mi = 0; mi < 4; mi++)
                #pragma unroll
                for (int nj = 0; nj < 4; nj++)
                    mma_bf16(acc[mi*4+nj], Ahi[mi], Bf[nj][0], Bf[nj][1]);
            // Alo x Bhi
            #pragma unroll
            for (int mi = 0; mi < 4; mi++) {
                int row = wm * 64 + mi * 16 + frow;
                uint32_t ad = (uint32_t)(row * 128) + (off ^ ((row << 4) & 0x70));
                ldm_x4(Alo[mi], sb + PJ_ALO + ad);
            }
            #pragma unroll
            for (int mi = 0; mi < 4; mi++)
                #pragma unroll
                for (int nj = 0; nj < 4; nj++)
                    mma_bf16(acc[mi*4+nj], Alo[mi], Bf[nj][0], Bf[nj][1]);
            // Ahi x Blo (reuse Bf)
            #pragma unroll
            for (int nf = 0; nf < 2; nf++) {
                uint32_t r[4];
                int row = wn * 32 + nf * 16 + frow;
                uint32_t ad = (uint32_t)(row * 128) + (off ^ ((row << 4) & 0x70));
                ldm_x4(r, sb + PJ_BLO + ad);
                Bf[nf*2][0] = r[0]; Bf[nf*2][1] = r[2];
                Bf[nf*2+1][0] = r[1]; Bf[nf*2+1][1] = r[3];
            }
            #pragma unroll
            for (int mi = 0; mi < 4; mi++)
                #pragma unroll
                for (int nj = 0; nj < 4; nj++)
                    mma_bf16(acc[mi*4+nj], Ahi[mi], Bf[nj][0], Bf[nj][1]);
        }
        __syncthreads();
    }
}

// ---------------- QKV projection ----------------
__global__ __launch_bounds__(256) void mma_qkv_kernel(
    const float* __restrict__ key, const float* __restrict__ value, const float* __restrict__ query,
    const float* __restrict__ Wq, const float* __restrict__ bq,
    const float* __restrict__ Wk, const float* __restrict__ bk,
    const float* __restrict__ Wv, const float* __restrict__ bv)
{
    extern __shared__ __align__(128) char sm[];
    const uint32_t sb = smem_u32(sm);
    const int z = blockIdx.z;
    const float* X    = (z == 0) ? query : (z == 1) ? key : value;
    const float* W    = (z == 0) ? Wq    : (z == 1) ? Wk  : Wv;
    const float* bias = (z == 0) ? bq    : (z == 1) ? bk  : bv;
    const int m0 = blockIdx.y * 128, n0 = blockIdx.x * 128;

    float acc[16][4];
    #pragma unroll
    for (int i = 0; i < 16; i++)
        #pragma unroll
        for (int j = 0; j < 4; j++) acc[i][j] = 0.0f;

    mma_gemm_core(X, W, sm, sb, m0, n0, acc);

    const int lane = threadIdx.x & 31, wid = threadIdx.x >> 5;
    const int wm = wid >> 2, wn = wid & 3;
    const float scale = (z == 0) ? 0.125f : 1.0f;

    #pragma unroll
    for (int mi = 0; mi < 4; mi++) {
        #pragma unroll
        for (int half = 0; half < 2; half++) {
            const int row = m0 + wm * 64 + mi * 16 + (lane >> 2) + half * 8;
            const int b = row >> 11, s = row & 2047;
            #pragma unroll
            for (int nj = 0; nj < 4; nj++) {
                const int col = n0 + wn * 32 + nj * 8 + (lane & 3) * 2;
                float v0 = (acc[mi*4+nj][half*2+0] + bias[col])     * scale;
                float v1 = (acc[mi*4+nj][half*2+1] + bias[col + 1]) * scale;
                __nv_bfloat16 h0 = __float2bfloat16_rn(v0);
                __nv_bfloat16 h1 = __float2bfloat16_rn(v1);
                __nv_bfloat16 l0 = __float2bfloat16_rn(v0 - __bfloat162float(h0));
                __nv_bfloat16 l1 = __float2bfloat16_rn(v1 - __bfloat162float(h1));
                const int hh = col >> 6, dh = col & 63;
                if (z == 0) {
                    size_t o = ((size_t)(b * NH + hh) * NS + s) * NDH + dh;
                    *(__nv_bfloat162*)&g_Qhi[o] = __nv_bfloat162(h0, h1);
                    *(__nv_bfloat162*)&g_Qlo[o] = __nv_bfloat162(l0, l1);
                } else if (z == 1) {
                    size_t o = ((size_t)(b * NH + hh) * NS + s) * NDH + dh;
                    *(__nv_bfloat162*)&g_Khi[o] = __nv_bfloat162(h0, h1);
                    *(__nv_bfloat162*)&g_Klo[o] = __nv_bfloat162(l0, l1);
                } else {
                    size_t o = ((size_t)(b * NH + hh) * NDH + dh) * NS + s;
                    g_Vhi[o] = h0; g_Vlo[o] = l0;
                    g_Vhi[o + NS] = h1; g_Vlo[o + NS] = l1;
                }
            }
        }
    }
}

// ---------------- output projection ----------------
__global__ __launch_bounds__(256) void mma_out_kernel(
    const float* __restrict__ Wo, const float* __restrict__ bo, float* __restrict__ out)
{
    extern __shared__ __align__(128) char sm[];
    const uint32_t sb = smem_u32(sm);
    const int m0 = blockIdx.y * 128, n0 = blockIdx.x * 128;

    float acc[16][4];
    #pragma unroll
    for (int i = 0; i < 16; i++)
        #pragma unroll
        for (int j = 0; j < 4; j++) acc[i][j] = 0.0f;

    mma_gemm_core(g_ctx, Wo, sm, sb, m0, n0, acc);

    const int lane = threadIdx.x & 31, wid = threadIdx.x >> 5;
    const int wm = wid >> 2, wn = wid & 3;

    #pragma unroll
    for (int mi = 0; mi < 4; mi++) {
        #pragma unroll
        for (int half = 0; half < 2; half++) {
            const int row = m0 + wm * 64 + mi * 16 + (lane >> 2) + half * 8;
            #pragma unroll
            for (int nj = 0; nj < 4; nj++) {
                const int col = n0 + wn * 32 + nj * 8 + (lane & 3) * 2;
                float2 v = make_float2(acc[mi*4+nj][half*2+0] + bo[col],
                                       acc[mi*4+nj][half*2+1] + bo[col + 1]);
                *(float2*)&out[(size_t)row * ND + col] = v;
            }
        }
    }
}

// ---------------- mask dtype detection ----------------
__global__ void detect_mask_kernel(const void* mask) {
    __shared__ int sF, sI;
    if (threadIdx.x == 0) { sF = 1; sI = 1; }
    __syncthreads();
    unsigned w = ((const unsigned*)mask)[threadIdx.x];
    if (!(w == 0u || w == 0x3F800000u)) sF = 0;
    if (!(w == 0u || w == 1u)) sI = 0;
    __syncthreads();
    if (threadIdx.x == 0) g_mode = sF ? 0 : (sI ? 1 : 2);
}

// ---------------- mask bit-packing ----------------
__global__ void maskprep_kernel(const void* mask) {
    int w = blockIdx.x * blockDim.x + threadIdx.x;
    int mode = g_mode;
    unsigned bits = 0;
    size_t base = (size_t)w * 32;
    if (mode == 0) {
        const float* mf = (const float*)mask;
        #pragma unroll 8
        for (int j = 0; j < 32; j++) bits |= (mf[base + j] != 0.0f ? 1u : 0u) << j;
    } else if (mode == 1) {
        const int* mi = (const int*)mask;
        #pragma unroll 8
        for (int j = 0; j < 32; j++) bits |= (mi[base + j] != 0 ? 1u : 0u) << j;
    } else {
        const unsigned char* mb = (const unsigned char*)mask;
        #pragma unroll 8
        for (int j = 0; j < 32; j++) bits |= (mb[base + j] != 0 ? 1u : 0u) << j;
    }
    g_maskbits[w] = bits;
}

// ---------------- T5 relative-position bias table ----------------
__global__ void biastab_kernel(const float* __restrict__ rel_bias) {
    int t = blockIdx.x * blockDim.x + threadIdx.x;
    if (t >= NH * 4096) return;
    int h = t >> 12;
    int dix = t & 4095;
    int delta = dix - 2047;               // delta = k - q
    int rb = (delta > 0) ? 16 : 0;
    int ad = abs(delta);
    int bucket;
    if (ad < 8) {
        bucket = rb + ad;
    } else {
        float fl = logf((float)ad / 8.0f) / logf(16.0f) * 8.0f;
        int l = (int)fl;
        int lg = 8 + l; if (lg > 15) lg = 15;
        bucket = rb + lg;
    }
    g_biasT[t] = rel_bias[bucket * NH + h];
}

// ---------------- flash attention on mma.sync ----------------
#define AT_QHI 0
#define AT_QLO 16384
#define AT_KHI 32768
#define AT_KLO 40960
#define AT_VHI 49152
#define AT_VLO 57344
#define AT_BIAS 65536
#define AT_TOTAL (65536 + 1024)

__global__ __launch_bounds__(256) void attn_kernel() {
    extern __shared__ __align__(128) char sm[];
    const uint32_t sb = smem_u32(sm);
    float* Bsm = (float*)(sm + AT_BIAS);

    const int b = blockIdx.z, h = blockIdx.y;
    const int bh = b * NH + h;
    const int q0 = blockIdx.x * 128;
    const int tid = threadIdx.x, lane = tid & 31, wid = tid >> 5;
    const int mat = lane >> 3;
    const int frow = (mat & 1) * 8 + (lane & 7);
    const int fpart = (mat >> 1) * 16;

    const unsigned* Mg = g_maskbits + (size_t)b * NS * (NS / 32);
    const float* Bt = g_biasT + (h << 12);

    // load Q tile (128 x 64, hi/lo) once: 128 rows x 8 chunks = 1024 uint4
    {
        const char* srcH = (const char*)g_Qhi + ((size_t)bh * NS + q0) * NDH * 2;
        const char* srcL = (const char*)g_Qlo + ((size_t)bh * NS + q0) * NDH * 2;
        #pragma unroll
        for (int i = 0; i < 4; i++) {
            int f = tid + i * 256;
            int row = f >> 3, ch = (f & 7) * 16;
            uint32_t d = (uint32_t)(row * 128) + ((uint32_t)ch ^ ((row << 4) & 0x70));
            *(uint4*)(sm + AT_QHI + d) = *(const uint4*)(srcH + row * 128 + ch);
            *(uint4*)(sm + AT_QLO + d) = *(const uint4*)(srcL + row * 128 + ch);
        }
    }

    float mrow0 = -1e30f, mrow1 = -1e30f, lsum0 = 0.0f, lsum1 = 0.0f;
    float o[8][4];
    #pragma unroll
    for (int j = 0; j < 8; j++)
        #pragma unroll
        for (int c = 0; c < 4; c++) o[j][c] = 0.0f;

    const int qloc0 = wid * 16 + (lane >> 2);
    const int qloc1 = qloc0 + 8;

    for (int k0 = 0; k0 < NS; k0 += 64) {
        // copy K (64x64 [k][d]) and V^T (64x64 [dh][s]) hi/lo
        {
            const char* kH = (const char*)g_Khi + ((size_t)bh * NS + k0) * NDH * 2;
            const char* kL = (const char*)g_Klo + ((size_t)bh * NS + k0) * NDH * 2;
            const char* vH = (const char*)g_Vhi + ((size_t)bh * NDH * NS + k0) * 2;
            const char* vL = (const char*)g_Vlo + ((size_t)bh * NDH * NS + k0) * 2;
            #pragma unroll
            for (int i = 0; i < 2; i++) {
                int f = tid + i * 256;
                int row = f >> 3, ch = (f & 7) * 16;
                uint32_t d = (uint32_t)(row * 128) + ((uint32_t)ch ^ ((row << 4) & 0x70));
                *(uint4*)(sm + AT_KHI + d) = *(const uint4*)(kH + row * 128 + ch);
                *(uint4*)(sm + AT_KLO + d) = *(const uint4*)(kL + row * 128 + ch);
                *(uint4*)(sm + AT_VHI + d) = *(const uint4*)(vH + (size_t)row * NS * 2 + ch);
                *(uint4*)(sm + AT_VLO + d) = *(const uint4*)(vL + (size_t)row * NS * 2 + ch);
            }
        }
        if (tid < 192) {
            int gi = k0 - q0 + 1920 + tid;
            gi = gi < 0 ? 0 : (gi > 4095 ? 4095 : gi);
            Bsm[tid] = Bt[gi];
        }
        __syncthreads();

        // S = Q K^T  (3-pass)
        float s[8][4];
        #pragma unroll
        for (int j = 0; j < 8; j++)
            #pragma unroll
            for (int c = 0; c < 4; c++) s[j][c] = 0.0f;

        #pragma unroll
        for (int ks = 0; ks < 4; ks++) {
            const uint32_t off = (uint32_t)(ks * 32 + fpart);
            uint32_t qh[4], ql[4], Bf[8][2];
            {
                int row = wid * 16 + frow;
                uint32_t ad = (uint32_t)(row * 128) + (off ^ ((row << 4) & 0x70));
                ldm_x4(qh, sb + AT_QHI + ad);
                ldm_x4(ql, sb + AT_QLO + ad);
            }
            #pragma unroll
            for (int nf = 0; nf < 4; nf++) {
                uint32_t r[4];
                int row = nf * 16 + frow;
                uint32_t ad = (uint32_t)(row * 128) + (off ^ ((row << 4) & 0x70));
                ldm_x4(r, sb + AT_KHI + ad);
                Bf[nf*2][0] = r[0]; Bf[nf*2][1] = r[2];
                Bf[nf*2+1][0] = r[1]; Bf[nf*2+1][1] = r[3];
            }
            #pragma unroll
            for (int j = 0; j < 8; j++) mma_bf16(s[j], qh, Bf[j][0], Bf[j][1]);
            #pragma unroll
            for (int j = 0; j < 8; j++) mma_bf16(s[j], ql, Bf[j][0], Bf[j][1]);
            #pragma unroll
            for (int nf = 0; nf < 4; nf++) {
                uint32_t r[4];
                int row = nf * 16 + frow;
                uint32_t ad = (uint32_t)(row * 128) + (off ^ ((row << 4) & 0x70));
                ldm_x4(r, sb + AT_KLO + ad);
                Bf[nf*2][0] = r[0]; Bf[nf*2][1] = r[2];
                Bf[nf*2+1][0] = r[1]; Bf[nf*2+1][1] = r[3];
            }
            #pragma unroll
            for (int j = 0; j < 8; j++) mma_bf16(s[j], qh, Bf[j][0], Bf[j][1]);
        }

        // bias + mask
        {
            const size_t mrow_base0 = (size_t)(q0 + qloc0) * (NS / 32) + (k0 >> 5);
            const size_t mrow_base1 = (size_t)(q0 + qloc1) * (NS / 32) + (k0 >> 5);
            unsigned w00 = Mg[mrow_base0], w01 = Mg[mrow_base0 + 1];
            unsigned w10 = Mg[mrow_base1], w11 = Mg[mrow_base1 + 1];
            const int bb0 = 127 - qloc0, bb1 = 127 - qloc1;
            #pragma unroll
            for (int j = 0; j < 8; j++) {
                int kk = j * 8 + (lane & 3) * 2;
                unsigned wa = (j < 4) ? w00 : w01;
                unsigned wb = (j < 4) ? w10 : w11;
                float s0 = s[j][0] + Bsm[kk + bb0];
                float s1 = s[j][1] + Bsm[kk + 1 + bb0];
                float s2 = s[j][2] + Bsm[kk + bb1];
                float s3 = s[j][3] + Bsm[kk + 1 + bb1];
                s[j][0] = ((wa >> (kk & 31)) & 1u)       ? -1e18f : s0;
                s[j][1] = ((wa >> ((kk + 1) & 31)) & 1u) ? -1e18f : s1;
                s[j][2] = ((wb >> (kk & 31)) & 1u)       ? -1e18f : s2;
                s[j][3] = ((wb >> ((kk + 1) & 31)) & 1u) ? -1e18f : s3;
            }
        }

        // softmax (online)
        float rm0 = -1e30f, rm1 = -1e30f;
        #pragma unroll
        for (int j = 0; j < 8; j++) {
            rm0 = fmaxf(rm0, fmaxf(s[j][0], s[j][1]));
            rm1 = fmaxf(rm1, fmaxf(s[j][2], s[j][3]));
        }
        rm0 = fmaxf(rm0, __shfl_xor_sync(0xffffffffu, rm0, 1));
        rm0 = fmaxf(rm0, __shfl_xor_sync(0xffffffffu, rm0, 2));
        rm1 = fmaxf(rm1, __shfl_xor_sync(0xffffffffu, rm1, 1));
        rm1 = fmaxf(rm1, __shfl_xor_sync(0xffffffffu, rm1, 2));
        float mn0 = fmaxf(mrow0, rm0), mn1 = fmaxf(mrow1, rm1);
        float al0 = __expf(mrow0 - mn0), al1 = __expf(mrow1 - mn1);
        mrow0 = mn0; mrow1 = mn1;
        float rs0 = 0.0f, rs1 = 0.0f;
        #pragma unroll
        for (int j = 0; j < 8; j++) {
            s[j][0] = __expf(s[j][0] - mn0); rs0 += s[j][0];
            s[j][1] = __expf(s[j][1] - mn0); rs0 += s[j][1];
            s[j][2] = __expf(s[j][2] - mn1); rs1 += s[j][2];
            s[j][3] = __expf(s[j][3] - mn1); rs1 += s[j][3];
        }
        rs0 += __shfl_xor_sync(0xffffffffu, rs0, 1);
        rs0 += __shfl_xor_sync(0xffffffffu, rs0, 2);
        rs1 += __shfl_xor_sync(0xffffffffu, rs1, 1);
        rs1 += __shfl_xor_sync(0xffffffffu, rs1, 2);
        lsum0 = lsum0 * al0 + rs0;
        lsum1 = lsum1 * al1 + rs1;
        #pragma unroll
        for (int j = 0; j < 8; j++) {
            o[j][0] *= al0; o[j][1] *= al0;
            o[j][2] *= al1; o[j][3] *= al1;
        }

        // P -> A fragments, hi + lo residual (no smem round trip)
        uint32_t pa[4][4], pl[4][4];
        #pragma unroll
        for (int ks = 0; ks < 4; ks++) {
            split_pack(s[2*ks][0],   s[2*ks][1],   pa[ks][0], pl[ks][0]);
            split_pack(s[2*ks][2],   s[2*ks][3],   pa[ks][1], pl[ks][1]);
            split_pack(s[2*ks+1][0], s[2*ks+1][1], pa[ks][2], pl[ks][2]);
            split_pack(s[2*ks+1][2], s[2*ks+1][3], pa[ks][3], pl[ks][3]);
        }

        // O += P V  (3-pass: Phi*Vhi + Plo*Vhi (reuses Vhi frags) + Phi*Vlo)
        #pragma unroll
        for (int ks = 0; ks < 4; ks++) {
            const uint32_t off = (uint32_t)(ks * 32 + fpart);
            uint32_t Vf[8][2];
            #pragma unroll
            for (int nf = 0; nf < 4; nf++) {
                uint32_t r[4];
                int row = nf * 16 + frow;
                uint32_t ad = (uint32_t)(row * 128) + (off ^ ((row << 4) & 0x70));
                ldm_x4(r, sb + AT_VHI + ad);
                Vf[nf*2][0] = r[0]; Vf[nf*2][1] = r[2];
                Vf[nf*2+1][0] = r[1]; Vf[nf*2+1][1] = r[3];
            }
            #pragma unroll
            for (int j = 0; j < 8; j++) mma_bf16(o[j], pa[ks], Vf[j][0], Vf[j][1]);
            #pragma unroll
            for (int j = 0; j < 8; j++) mma_bf16(o[j], pl[ks], Vf[j][0], Vf[j][1]);
            #pragma unroll
            for (int nf = 0; nf < 4; nf++) {
                uint32_t r[4];
                int row = nf * 16 + frow;
                uint32_t ad = (uint32_t)(row * 128) + (off ^ ((row << 4) & 0x70));
                ldm_x4(r, sb + AT_VLO + ad);
                Vf[nf*2][0] = r[0]; Vf[nf*2][1] = r[2];
                Vf[nf*2+1][0] = r[1]; Vf[nf*2+1][1] = r[3];
            }
            #pragma unroll
            for (int j = 0; j < 8; j++) mma_bf16(o[j], pa[ks], Vf[j][0], Vf[j][1]);
        }
        __syncthreads();
    }

    const float inv0 = 1.0f / lsum0, inv1 = 1.0f / lsum1;
    #pragma unroll
    for (int j = 0; j < 8; j++) {
        const int col = h * NDH + j * 8 + (lane & 3) * 2;
        *(float2*)&g_ctx[(size_t)(b * NS + q0 + qloc0) * ND + col] =
            make_float2(o[j][0] * inv0, o[j][1] * inv0);
        *(float2*)&g_ctx[(size_t)(b * NS + q0 + qloc1) * ND + col] =
            make_float2(o[j][2] * inv1, o[j][3] * inv1);
    }
}

// ---------------- launch ----------------
extern "C" void kernel_launch(void* const* d_in, const int* in_sizes, int n_in,
                              void* d_out, int out_size) {
    const float* key      = (const float*)d_in[0];
    const float* value    = (const float*)d_in[1];
    const float* query    = (const float*)d_in[2];
    const float* Wq       = (const float*)d_in[3];
    const float* bq       = (const float*)d_in[4];
    const float* Wk       = (const float*)d_in[5];
    const float* bk       = (const float*)d_in[6];
    const float* Wv       = (const float*)d_in[7];
    const float* bv       = (const float*)d_in[8];
    const float* Wo       = (const float*)d_in[9];
    const float* bo       = (const float*)d_in[10];
    const float* rel_bias = (const float*)d_in[11];
    const void*  mask     = (const void*)d_in[12];
    float* out = (float*)d_out;

    cudaFuncSetAttribute(attn_kernel, cudaFuncAttributeMaxDynamicSharedMemorySize, AT_TOTAL);
    cudaFuncSetAttribute(mma_qkv_kernel, cudaFuncAttributeMaxDynamicSharedMemorySize, PJ_TOTAL);
    cudaFuncSetAttribute(mma_out_kernel, cudaFuncAttributeMaxDynamicSharedMemorySize, PJ_TOTAL);

    detect_mask_kernel<<<1, 1024>>>(mask);
    maskprep_kernel<<<(NB * NS * NS / 32) / 256, 256>>>(mask);
    biastab_kernel<<<(NH * 4096) / 256, 256>>>(rel_bias);

    dim3 pgrid(ND / 128, (NB * NS) / 128, 3);
    mma_qkv_kernel<<<pgrid, 256, PJ_TOTAL>>>(key, value, query, Wq, bq, Wk, bk, Wv, bv);

    dim3 agrid(NS / 128, NH, NB);
    attn_kernel<<<agrid, 256, AT_TOTAL>>>();

    dim3 ogrid(ND / 128, (NB * NS) / 128);
    mma_out_kernel<<<ogrid, 256, PJ_TOTAL>>>(Wo, bo, out);
}

// round 8
// speedup vs baseline: 2.1940x; 1.2310x over previous
#include <cuda_runtime.h>
#include <cuda_bf16.h>
#include <cstdint>

#define NB 4
#define NS 2048
#define ND 512
#define NH 8
#define NDH 64
#define XSZ (NB*NS*ND)          // 4194304 = 2^22
#define WSZ (ND*ND)             // 262144

// ---------------- scratch (device globals; no allocations) ----------------
__device__ __nv_bfloat16 g_Xhi[(size_t)3*XSZ], g_Xlo[(size_t)3*XSZ];   // q,k,v inputs [m][k]
__device__ __nv_bfloat16 g_Wthi[(size_t)4*WSZ], g_Wtlo[(size_t)4*WSZ]; // Wq,Wk,Wv,Wo as [n][k]
__device__ __nv_bfloat16 g_Chi[(size_t)XSZ], g_Clo[(size_t)XSZ];       // ctx [m][k]
__device__ __nv_bfloat16 g_Qhi[(size_t)NB*NH*NS*NDH];   // [bh][s][dh]
__device__ __nv_bfloat16 g_Qlo[(size_t)NB*NH*NS*NDH];
__device__ __nv_bfloat16 g_Khi[(size_t)NB*NH*NS*NDH];   // [bh][s][dh]
__device__ __nv_bfloat16 g_Klo[(size_t)NB*NH*NS*NDH];
__device__ __nv_bfloat16 g_Vhi[(size_t)NB*NH*NDH*NS];   // [bh][dh][s]
__device__ __nv_bfloat16 g_Vlo[(size_t)NB*NH*NDH*NS];
__device__ float g_biasT[NH*4096];                      // [h][delta+2047]
__device__ unsigned g_maskbits[(size_t)NB*NS*NS/32];
__device__ int g_mode;

// ================= helpers =================
__device__ __forceinline__ uint32_t smem_u32(const void* p) {
    uint32_t a;
    asm("{ .reg .u64 t; cvta.to.shared.u64 t, %1; cvt.u32.u64 %0, t; }" : "=r"(a) : "l"(p));
    return a;
}

#define CP16(dst, src) asm volatile("cp.async.cg.shared.global [%0], [%1], 16;" \
    :: "r"((uint32_t)(dst)), "l"(__cvta_generic_to_global((const void*)(src))) : "memory")
#define CP_COMMIT() asm volatile("cp.async.commit_group;" ::: "memory")
#define CP_WAIT1()  asm volatile("cp.async.wait_group 1;" ::: "memory")
#define CP_WAIT0()  asm volatile("cp.async.wait_group 0;" ::: "memory")

__device__ __forceinline__ void ldm_x4(uint32_t (&r)[4], uint32_t addr) {
    asm volatile("ldmatrix.sync.aligned.m8n8.x4.shared.b16 {%0,%1,%2,%3}, [%4];"
        : "=r"(r[0]), "=r"(r[1]), "=r"(r[2]), "=r"(r[3]) : "r"(addr));
}

__device__ __forceinline__ void mma_bf16(float (&c)[4], const uint32_t (&a)[4],
                                         uint32_t b0, uint32_t b1) {
    asm volatile("mma.sync.aligned.m16n8k16.row.col.f32.bf16.bf16.f32 "
        "{%0,%1,%2,%3}, {%4,%5,%6,%7}, {%8,%9}, {%0,%1,%2,%3};"
        : "+f"(c[0]), "+f"(c[1]), "+f"(c[2]), "+f"(c[3])
        : "r"(a[0]), "r"(a[1]), "r"(a[2]), "r"(a[3]), "r"(b0), "r"(b1));
}

__device__ __forceinline__ uint32_t pack_bf16x2(float lo, float hi) {
    uint32_t d;
    asm("cvt.rn.bf16x2.f32 %0, %1, %2;" : "=r"(d) : "f"(hi), "f"(lo));
    return d;
}

__device__ __forceinline__ void split_pack(float a, float b, uint32_t& hi, uint32_t& lo) {
    __nv_bfloat16 ha = __float2bfloat16_rn(a);
    __nv_bfloat16 hb = __float2bfloat16_rn(b);
    hi = (uint32_t)__bfloat16_as_ushort(ha) | ((uint32_t)__bfloat16_as_ushort(hb) << 16);
    lo = pack_bf16x2(a - __bfloat162float(ha), b - __bfloat162float(hb));
}

// ================= prep: convert inputs / weights to bf16 hi+lo =================
__global__ void convert_x_kernel(const float* __restrict__ q, const float* __restrict__ k,
                                 const float* __restrict__ v) {
    size_t t = (size_t)blockIdx.x * 256 + threadIdx.x;
    size_t e = t * 4;
    int z = (int)(e >> 22);
    size_t rem = e & (size_t)(XSZ - 1);
    const float* src = (z == 0) ? q : (z == 1) ? k : v;
    float4 f = *(const float4*)&src[rem];
    __nv_bfloat162 h0 = __floats2bfloat162_rn(f.x, f.y);
    __nv_bfloat162 h1 = __floats2bfloat162_rn(f.z, f.w);
    __nv_bfloat162 l0 = __floats2bfloat162_rn(f.x - __bfloat162float(h0.x), f.y - __bfloat162float(h0.y));
    __nv_bfloat162 l1 = __floats2bfloat162_rn(f.z - __bfloat162float(h1.x), f.w - __bfloat162float(h1.y));
    *(__nv_bfloat162*)&g_Xhi[e]     = h0;
    *(__nv_bfloat162*)&g_Xhi[e + 2] = h1;
    *(__nv_bfloat162*)&g_Xlo[e]     = l0;
    *(__nv_bfloat162*)&g_Xlo[e + 2] = l1;
}

__global__ void convert_w_kernel(const float* __restrict__ Wq, const float* __restrict__ Wk,
                                 const float* __restrict__ Wv, const float* __restrict__ Wo) {
    __shared__ float tile[32][33];
    const int m = blockIdx.z;
    const float* W = (m == 0) ? Wq : (m == 1) ? Wk : (m == 2) ? Wv : Wo;
    const int k0 = blockIdx.x * 32, n0 = blockIdx.y * 32;
    const int tx = threadIdx.x, ty = threadIdx.y;
    #pragma unroll
    for (int i = 0; i < 4; i++)
        tile[ty + i * 8][tx] = W[(size_t)(k0 + ty + i * 8) * ND + n0 + tx];
    __syncthreads();
    #pragma unroll
    for (int i = 0; i < 4; i++) {
        int n = n0 + ty + i * 8;
        float v = tile[tx][ty + i * 8];          // = W[k0+tx][n]
        __nv_bfloat16 h = __float2bfloat16_rn(v);
        __nv_bfloat16 l = __float2bfloat16_rn(v - __bfloat162float(h));
        size_t o = (size_t)m * WSZ + (size_t)n * ND + k0 + tx;
        g_Wthi[o] = h; g_Wtlo[o] = l;
    }
}

// ================= GEMM core (pure bf16, cp.async double-buffered, 3-pass) =================
#define PJ_STAGE 65536
#define PJ_SMEM  131072
// in-stage: AHI +0, ALO +16384, BHI +32768, BLO +49152 (each 128 rows x 128B, SW128)

__device__ __forceinline__ void pj_load_stage(uint32_t st, const char* AhiB, const char* AloB,
                                              const char* BhiB, const char* BloB, int k0, int tid) {
    const size_t ko = (size_t)k0 * 2;
    #pragma unroll
    for (int i = 0; i < 4; i++) {
        int j = tid + i * 256;
        int row = j >> 3, ch = (j & 7) * 16;
        uint32_t d = (uint32_t)(row * 128) + ((uint32_t)ch ^ ((row << 4) & 0x70));
        size_t so = (size_t)row * 1024 + ko + ch;
        CP16(st + d,         AhiB + so);
        CP16(st + 16384 + d, AloB + so);
        CP16(st + 32768 + d, BhiB + so);
        CP16(st + 49152 + d, BloB + so);
    }
}

__device__ __forceinline__ void gemm_core_bf16(
    const __nv_bfloat16* Ahi, const __nv_bfloat16* Alo,
    const __nv_bfloat16* Bhi, const __nv_bfloat16* Blo,
    uint32_t sb, int m0, int n0, float (&acc)[16][4])
{
    const int tid = threadIdx.x;
    const int lane = tid & 31, wid = tid >> 5;
    const int wm = wid >> 2, wn = wid & 3;
    const int mat = lane >> 3;
    const int frow = (mat & 1) * 8 + (lane & 7);
    const int fpart = (mat >> 1) * 16;

    const char* AhiB = (const char*)Ahi + (size_t)m0 * 1024;
    const char* AloB = (const char*)Alo + (size_t)m0 * 1024;
    const char* BhiB = (const char*)Bhi + (size_t)n0 * 1024;
    const char* BloB = (const char*)Blo + (size_t)n0 * 1024;

    pj_load_stage(sb, AhiB, AloB, BhiB, BloB, 0, tid);
    CP_COMMIT();

    for (int c = 0; c < 8; c++) {
        const uint32_t cur = sb + (uint32_t)(c & 1) * PJ_STAGE;
        if (c < 7) {
            pj_load_stage(sb + (uint32_t)((c + 1) & 1) * PJ_STAGE, AhiB, AloB, BhiB, BloB,
                          (c + 1) * 64, tid);
            CP_COMMIT();
            CP_WAIT1();
        } else {
            CP_WAIT0();
        }
        __syncthreads();

        #pragma unroll
        for (int ks = 0; ks < 4; ks++) {
            const uint32_t off = (uint32_t)(ks * 32 + fpart);
            uint32_t Af[4][4], Al[4][4], Bf[4][2];
            #pragma unroll
            for (int mi = 0; mi < 4; mi++) {
                int row = wm * 64 + mi * 16 + frow;
                uint32_t ad = (uint32_t)(row * 128) + (off ^ ((row << 4) & 0x70));
                ldm_x4(Af[mi], cur + ad);
            }
            #pragma unroll
            for (int nf = 0; nf < 2; nf++) {
                uint32_t r[4];
                int row = wn * 32 + nf * 16 + frow;
                uint32_t ad = (uint32_t)(row * 128) + (off ^ ((row << 4) & 0x70));
                ldm_x4(r, cur + 32768 + ad);
                Bf[nf*2][0] = r[0]; Bf[nf*2][1] = r[2];
                Bf[nf*2+1][0] = r[1]; Bf[nf*2+1][1] = r[3];
            }
            #pragma unroll
            for (int mi = 0; mi < 4; mi++)
                #pragma unroll
                for (int nj = 0; nj < 4; nj++)
                    mma_bf16(acc[mi*4+nj], Af[mi], Bf[nj][0], Bf[nj][1]);
            // Alo x Bhi
            #pragma unroll
            for (int mi = 0; mi < 4; mi++) {
                int row = wm * 64 + mi * 16 + frow;
                uint32_t ad = (uint32_t)(row * 128) + (off ^ ((row << 4) & 0x70));
                ldm_x4(Al[mi], cur + 16384 + ad);
            }
            #pragma unroll
            for (int mi = 0; mi < 4; mi++)
                #pragma unroll
                for (int nj = 0; nj < 4; nj++)
                    mma_bf16(acc[mi*4+nj], Al[mi], Bf[nj][0], Bf[nj][1]);
            // Ahi x Blo
            #pragma unroll
            for (int nf = 0; nf < 2; nf++) {
                uint32_t r[4];
                int row = wn * 32 + nf * 16 + frow;
                uint32_t ad = (uint32_t)(row * 128) + (off ^ ((row << 4) & 0x70));
                ldm_x4(r, cur + 49152 + ad);
                Bf[nf*2][0] = r[0]; Bf[nf*2][1] = r[2];
                Bf[nf*2+1][0] = r[1]; Bf[nf*2+1][1] = r[3];
            }
            #pragma unroll
            for (int mi = 0; mi < 4; mi++)
                #pragma unroll
                for (int nj = 0; nj < 4; nj++)
                    mma_bf16(acc[mi*4+nj], Af[mi], Bf[nj][0], Bf[nj][1]);
        }
        __syncthreads();
    }
}

// ---------------- QKV projection ----------------
__global__ __launch_bounds__(256) void mma_qkv_kernel(
    const float* __restrict__ bq, const float* __restrict__ bk, const float* __restrict__ bv)
{
    extern __shared__ __align__(1024) char sm[];
    const uint32_t sb = smem_u32(sm);
    const int z = blockIdx.z;
    const float* bias = (z == 0) ? bq : (z == 1) ? bk : bv;
    const int m0 = blockIdx.y * 128, n0 = blockIdx.x * 128;

    float acc[16][4];
    #pragma unroll
    for (int i = 0; i < 16; i++)
        #pragma unroll
        for (int j = 0; j < 4; j++) acc[i][j] = 0.0f;

    gemm_core_bf16(g_Xhi + (size_t)z * XSZ, g_Xlo + (size_t)z * XSZ,
                   g_Wthi + (size_t)z * WSZ, g_Wtlo + (size_t)z * WSZ,
                   sb, m0, n0, acc);

    const int lane = threadIdx.x & 31, wid = threadIdx.x >> 5;
    const int wm = wid >> 2, wn = wid & 3;
    const float scale = (z == 0) ? 0.125f : 1.0f;

    #pragma unroll
    for (int mi = 0; mi < 4; mi++) {
        #pragma unroll
        for (int half = 0; half < 2; half++) {
            const int row = m0 + wm * 64 + mi * 16 + (lane >> 2) + half * 8;
            const int b = row >> 11, s = row & 2047;
            #pragma unroll
            for (int nj = 0; nj < 4; nj++) {
                const int col = n0 + wn * 32 + nj * 8 + (lane & 3) * 2;
                float v0 = (acc[mi*4+nj][half*2+0] + bias[col])     * scale;
                float v1 = (acc[mi*4+nj][half*2+1] + bias[col + 1]) * scale;
                __nv_bfloat16 h0 = __float2bfloat16_rn(v0);
                __nv_bfloat16 h1 = __float2bfloat16_rn(v1);
                __nv_bfloat16 l0 = __float2bfloat16_rn(v0 - __bfloat162float(h0));
                __nv_bfloat16 l1 = __float2bfloat16_rn(v1 - __bfloat162float(h1));
                const int hh = col >> 6, dh = col & 63;
                if (z == 0) {
                    size_t o = ((size_t)(b * NH + hh) * NS + s) * NDH + dh;
                    *(__nv_bfloat162*)&g_Qhi[o] = __nv_bfloat162(h0, h1);
                    *(__nv_bfloat162*)&g_Qlo[o] = __nv_bfloat162(l0, l1);
                } else if (z == 1) {
                    size_t o = ((size_t)(b * NH + hh) * NS + s) * NDH + dh;
                    *(__nv_bfloat162*)&g_Khi[o] = __nv_bfloat162(h0, h1);
                    *(__nv_bfloat162*)&g_Klo[o] = __nv_bfloat162(l0, l1);
                } else {
                    size_t o = ((size_t)(b * NH + hh) * NDH + dh) * NS + s;
                    g_Vhi[o] = h0; g_Vlo[o] = l0;
                    g_Vhi[o + NS] = h1; g_Vlo[o + NS] = l1;
                }
            }
        }
    }
}

// ---------------- output projection ----------------
__global__ __launch_bounds__(256) void mma_out_kernel(
    const float* __restrict__ bo, float* __restrict__ out)
{
    extern __shared__ __align__(1024) char sm[];
    const uint32_t sb = smem_u32(sm);
    const int m0 = blockIdx.y * 128, n0 = blockIdx.x * 128;

    float acc[16][4];
    #pragma unroll
    for (int i = 0; i < 16; i++)
        #pragma unroll
        for (int j = 0; j < 4; j++) acc[i][j] = 0.0f;

    gemm_core_bf16(g_Chi, g_Clo, g_Wthi + (size_t)3 * WSZ, g_Wtlo + (size_t)3 * WSZ,
                   sb, m0, n0, acc);

    const int lane = threadIdx.x & 31, wid = threadIdx.x >> 5;
    const int wm = wid >> 2, wn = wid & 3;

    #pragma unroll
    for (int mi = 0; mi < 4; mi++) {
        #pragma unroll
        for (int half = 0; half < 2; half++) {
            const int row = m0 + wm * 64 + mi * 16 + (lane >> 2) + half * 8;
            #pragma unroll
            for (int nj = 0; nj < 4; nj++) {
                const int col = n0 + wn * 32 + nj * 8 + (lane & 3) * 2;
                float2 v = make_float2(acc[mi*4+nj][half*2+0] + bo[col],
                                       acc[mi*4+nj][half*2+1] + bo[col + 1]);
                *(float2*)&out[(size_t)row * ND + col] = v;
            }
        }
    }
}

// ---------------- mask dtype detection ----------------
__global__ void detect_mask_kernel(const void* mask) {
    __shared__ int sF, sI;
    if (threadIdx.x == 0) { sF = 1; sI = 1; }
    __syncthreads();
    unsigned w = ((const unsigned*)mask)[threadIdx.x];
    if (!(w == 0u || w == 0x3F800000u)) sF = 0;
    if (!(w == 0u || w == 1u)) sI = 0;
    __syncthreads();
    if (threadIdx.x == 0) g_mode = sF ? 0 : (sI ? 1 : 2);
}

// ---------------- mask bit-packing ----------------
__global__ void maskprep_kernel(const void* mask) {
    int w = blockIdx.x * blockDim.x + threadIdx.x;
    int mode = g_mode;
    unsigned bits = 0;
    size_t base = (size_t)w * 32;
    if (mode == 0) {
        const float* mf = (const float*)mask;
        #pragma unroll 8
        for (int j = 0; j < 32; j++) bits |= (mf[base + j] != 0.0f ? 1u : 0u) << j;
    } else if (mode == 1) {
        const int* mi = (const int*)mask;
        #pragma unroll 8
        for (int j = 0; j < 32; j++) bits |= (mi[base + j] != 0 ? 1u : 0u) << j;
    } else {
        const unsigned char* mb = (const unsigned char*)mask;
        #pragma unroll 8
        for (int j = 0; j < 32; j++) bits |= (mb[base + j] != 0 ? 1u : 0u) << j;
    }
    g_maskbits[w] = bits;
}

// ---------------- T5 relative-position bias table ----------------
__global__ void biastab_kernel(const float* __restrict__ rel_bias) {
    int t = blockIdx.x * blockDim.x + threadIdx.x;
    if (t >= NH * 4096) return;
    int h = t >> 12;
    int dix = t & 4095;
    int delta = dix - 2047;               // delta = k - q
    int rb = (delta > 0) ? 16 : 0;
    int ad = abs(delta);
    int bucket;
    if (ad < 8) {
        bucket = rb + ad;
    } else {
        float fl = logf((float)ad / 8.0f) / logf(16.0f) * 8.0f;
        int l = (int)fl;
        int lg = 8 + l; if (lg > 15) lg = 15;
        bucket = rb + lg;
    }
    g_biasT[t] = rel_bias[bucket * NH + h];
}

// ---------------- flash attention (mma.sync, cp.async double-buffered KV) ----------------
// smem: QHI 0, QLO 16384; stages at 32768 + p*33792:
//   KHI +0, KLO +8192, VHI +16384, VLO +24576, BIAS +32768 (768B)
#define AT_STAGE 33792
#define AT_TOTAL (32768 + 2*AT_STAGE)   // 100352

__device__ __forceinline__ void at_load_stage(uint32_t st, const char* kH, const char* kL,
                                              const char* vH, const char* vL,
                                              const float* biasSrc, int k0, int tid) {
    #pragma unroll
    for (int i = 0; i < 2; i++) {
        int j = tid + i * 256;
        int row = j >> 3, ch = (j & 7) * 16;
        uint32_t d = (uint32_t)(row * 128) + ((uint32_t)ch ^ ((row << 4) & 0x70));
        size_t kso = (size_t)(k0 + row) * 128 + ch;
        size_t vso = (size_t)row * (NS * 2) + (size_t)k0 * 2 + ch;
        CP16(st + d,         kH + kso);
        CP16(st + 8192 + d,  kL + kso);
        CP16(st + 16384 + d, vH + vso);
        CP16(st + 24576 + d, vL + vso);
    }
    if (tid < 48) CP16(st + 32768 + tid * 16, (const char*)biasSrc + tid * 16);
}

__global__ __launch_bounds__(256) void attn_kernel() {
    extern __shared__ __align__(1024) char sm[];
    const uint32_t sb = smem_u32(sm);

    const int b = blockIdx.z, h = blockIdx.y;
    const int bh = b * NH + h;
    const int q0 = blockIdx.x * 128;
    const int tid = threadIdx.x, lane = tid & 31, wid = tid >> 5;
    const int mat = lane >> 3;
    const int frow = (mat & 1) * 8 + (lane & 7);
    const int fpart = (mat >> 1) * 16;

    const unsigned* Mg = g_maskbits + (size_t)b * NS * (NS / 32);
    const float* Bt = g_biasT + (h << 12);

    const char* kH = (const char*)g_Khi + (size_t)bh * NS * NDH * 2;
    const char* kL = (const char*)g_Klo + (size_t)bh * NS * NDH * 2;
    const char* vH = (const char*)g_Vhi + (size_t)bh * NDH * NS * 2;
    const char* vL = (const char*)g_Vlo + (size_t)bh * NDH * NS * 2;

    // prefetch stage 0 (k0 = 0)
    at_load_stage(sb + 32768, kH, kL, vH, vL, Bt + (0 - q0 + 1920), 0, tid);
    CP_COMMIT();

    // load Q tile (128 x 64, hi/lo) once: 1024 uint4 per half
    {
        const char* srcH = (const char*)g_Qhi + ((size_t)bh * NS + q0) * NDH * 2;
        const char* srcL = (const char*)g_Qlo + ((size_t)bh * NS + q0) * NDH * 2;
        #pragma unroll
        for (int i = 0; i < 4; i++) {
            int f = tid + i * 256;
            int row = f >> 3, ch = (f & 7) * 16;
            uint32_t d = (uint32_t)(row * 128) + ((uint32_t)ch ^ ((row << 4) & 0x70));
            *(uint4*)(sm + d)         = *(const uint4*)(srcH + row * 128 + ch);
            *(uint4*)(sm + 16384 + d) = *(const uint4*)(srcL + row * 128 + ch);
        }
    }

    float mrow0 = -1e30f, mrow1 = -1e30f, lsum0 = 0.0f, lsum1 = 0.0f;
    float o[8][4];
    #pragma unroll
    for (int j = 0; j < 8; j++)
        #pragma unroll
        for (int c = 0; c < 4; c++) o[j][c] = 0.0f;

    const int qloc0 = wid * 16 + (lane >> 2);
    const int qloc1 = qloc0 + 8;

    for (int k0 = 0; k0 < NS; k0 += 64) {
        const int p = (k0 >> 6) & 1;
        const uint32_t st = sb + 32768 + (uint32_t)p * AT_STAGE;
        if (k0 + 64 < NS) {
            at_load_stage(sb + 32768 + (uint32_t)(p ^ 1) * AT_STAGE, kH, kL, vH, vL,
                          Bt + (k0 + 64 - q0 + 1920), k0 + 64, tid);
            CP_COMMIT();
            CP_WAIT1();
        } else {
            CP_WAIT0();
        }
        __syncthreads();
        const float* Bsm = (const float*)(sm + 32768 + (size_t)p * AT_STAGE + 32768);

        // S = Q K^T  (3-pass)
        float s[8][4];
        #pragma unroll
        for (int j = 0; j < 8; j++)
            #pragma unroll
            for (int c = 0; c < 4; c++) s[j][c] = 0.0f;

        #pragma unroll
        for (int ks = 0; ks < 4; ks++) {
            const uint32_t off = (uint32_t)(ks * 32 + fpart);
            uint32_t qh[4], ql[4], Bf[8][2];
            {
                int row = wid * 16 + frow;
                uint32_t ad = (uint32_t)(row * 128) + (off ^ ((row << 4) & 0x70));
                ldm_x4(qh, sb + ad);
                ldm_x4(ql, sb + 16384 + ad);
            }
            #pragma unroll
            for (int nf = 0; nf < 4; nf++) {
                uint32_t r[4];
                int row = nf * 16 + frow;
                uint32_t ad = (uint32_t)(row * 128) + (off ^ ((row << 4) & 0x70));
                ldm_x4(r, st + ad);
                Bf[nf*2][0] = r[0]; Bf[nf*2][1] = r[2];
                Bf[nf*2+1][0] = r[1]; Bf[nf*2+1][1] = r[3];
            }
            #pragma unroll
            for (int j = 0; j < 8; j++) mma_bf16(s[j], qh, Bf[j][0], Bf[j][1]);
            #pragma unroll
            for (int j = 0; j < 8; j++) mma_bf16(s[j], ql, Bf[j][0], Bf[j][1]);
            #pragma unroll
            for (int nf = 0; nf < 4; nf++) {
                uint32_t r[4];
                int row = nf * 16 + frow;
                uint32_t ad = (uint32_t)(row * 128) + (off ^ ((row << 4) & 0x70));
                ldm_x4(r, st + 8192 + ad);
                Bf[nf*2][0] = r[0]; Bf[nf*2][1] = r[2];
                Bf[nf*2+1][0] = r[1]; Bf[nf*2+1][1] = r[3];
            }
            #pragma unroll
            for (int j = 0; j < 8; j++) mma_bf16(s[j], qh, Bf[j][0], Bf[j][1]);
        }

        // bias + mask
        {
            const size_t mrow_base0 = (size_t)(q0 + qloc0) * (NS / 32) + (k0 >> 5);
            const size_t mrow_base1 = (size_t)(q0 + qloc1) * (NS / 32) + (k0 >> 5);
            unsigned w00 = Mg[mrow_base0], w01 = Mg[mrow_base0 + 1];
            unsigned w10 = Mg[mrow_base1], w11 = Mg[mrow_base1 + 1];
            const int bb0 = 127 - qloc0, bb1 = 127 - qloc1;
            #pragma unroll
            for (int j = 0; j < 8; j++) {
                int kk = j * 8 + (lane & 3) * 2;
                unsigned wa = (j < 4) ? w00 : w01;
                unsigned wb = (j < 4) ? w10 : w11;
                float s0 = s[j][0] + Bsm[kk + bb0];
                float s1 = s[j][1] + Bsm[kk + 1 + bb0];
                float s2 = s[j][2] + Bsm[kk + bb1];
                float s3 = s[j][3] + Bsm[kk + 1 + bb1];
                s[j][0] = ((wa >> (kk & 31)) & 1u)       ? -1e18f : s0;
                s[j][1] = ((wa >> ((kk + 1) & 31)) & 1u) ? -1e18f : s1;
                s[j][2] = ((wb >> (kk & 31)) & 1u)       ? -1e18f : s2;
                s[j][3] = ((wb >> ((kk + 1) & 31)) & 1u) ? -1e18f : s3;
            }
        }

        // softmax (online)
        float rm0 = -1e30f, rm1 = -1e30f;
        #pragma unroll
        for (int j = 0; j < 8; j++) {
            rm0 = fmaxf(rm0, fmaxf(s[j][0], s[j][1]));
            rm1 = fmaxf(rm1, fmaxf(s[j][2], s[j][3]));
        }
        rm0 = fmaxf(rm0, __shfl_xor_sync(0xffffffffu, rm0, 1));
        rm0 = fmaxf(rm0, __shfl_xor_sync(0xffffffffu, rm0, 2));
        rm1 = fmaxf(rm1, __shfl_xor_sync(0xffffffffu, rm1, 1));
        rm1 = fmaxf(rm1, __shfl_xor_sync(0xffffffffu, rm1, 2));
        float mn0 = fmaxf(mrow0, rm0), mn1 = fmaxf(mrow1, rm1);
        float al0 = __expf(mrow0 - mn0), al1 = __expf(mrow1 - mn1);
        mrow0 = mn0; mrow1 = mn1;
        float rs0 = 0.0f, rs1 = 0.0f;
        #pragma unroll
        for (int j = 0; j < 8; j++) {
            s[j][0] = __expf(s[j][0] - mn0); rs0 += s[j][0];
            s[j][1] = __expf(s[j][1] - mn0); rs0 += s[j][1];
            s[j][2] = __expf(s[j][2] - mn1); rs1 += s[j][2];
            s[j][3] = __expf(s[j][3] - mn1); rs1 += s[j][3];
        }
        rs0 += __shfl_xor_sync(0xffffffffu, rs0, 1);
        rs0 += __shfl_xor_sync(0xffffffffu, rs0, 2);
        rs1 += __shfl_xor_sync(0xffffffffu, rs1, 1);
        rs1 += __shfl_xor_sync(0xffffffffu, rs1, 2);
        lsum0 = lsum0 * al0 + rs0;
        lsum1 = lsum1 * al1 + rs1;
        #pragma unroll
        for (int j = 0; j < 8; j++) {
            o[j][0] *= al0; o[j][1] *= al0;
            o[j][2] *= al1; o[j][3] *= al1;
        }

        // P -> A fragments, hi + lo residual
        uint32_t pa[4][4], pl[4][4];
        #pragma unroll
        for (int ks = 0; ks < 4; ks++) {
            split_pack(s[2*ks][0],   s[2*ks][1],   pa[ks][0], pl[ks][0]);
            split_pack(s[2*ks][2],   s[2*ks][3],   pa[ks][1], pl[ks][1]);
            split_pack(s[2*ks+1][0], s[2*ks+1][1], pa[ks][2], pl[ks][2]);
            split_pack(s[2*ks+1][2], s[2*ks+1][3], pa[ks][3], pl[ks][3]);
        }

        // O += P V (3-pass: Phi*Vhi + Plo*Vhi + Phi*Vlo)
        #pragma unroll
        for (int ks = 0; ks < 4; ks++) {
            const uint32_t off = (uint32_t)(ks * 32 + fpart);
            uint32_t Vf[8][2];
            #pragma unroll
            for (int nf = 0; nf < 4; nf++) {
                uint32_t r[4];
                int row = nf * 16 + frow;
                uint32_t ad = (uint32_t)(row * 128) + (off ^ ((row << 4) & 0x70));
                ldm_x4(r, st + 16384 + ad);
                Vf[nf*2][0] = r[0]; Vf[nf*2][1] = r[2];
                Vf[nf*2+1][0] = r[1]; Vf[nf*2+1][1] = r[3];
            }
            #pragma unroll
            for (int j = 0; j < 8; j++) mma_bf16(o[j], pa[ks], Vf[j][0], Vf[j][1]);
            #pragma unroll
            for (int j = 0; j < 8; j++) mma_bf16(o[j], pl[ks], Vf[j][0], Vf[j][1]);
            #pragma unroll
            for (int nf = 0; nf < 4; nf++) {
                uint32_t r[4];
                int row = nf * 16 + frow;
                uint32_t ad = (uint32_t)(row * 128) + (off ^ ((row << 4) & 0x70));
                ldm_x4(r, st + 24576 + ad);
                Vf[nf*2][0] = r[0]; Vf[nf*2][1] = r[2];
                Vf[nf*2+1][0] = r[1]; Vf[nf*2+1][1] = r[3];
            }
            #pragma unroll
            for (int j = 0; j < 8; j++) mma_bf16(o[j], pa[ks], Vf[j][0], Vf[j][1]);
        }
        __syncthreads();
    }

    // epilogue: write ctx directly as bf16 hi/lo (consumed by output projection)
    const float inv0 = 1.0f / lsum0, inv1 = 1.0f / lsum1;
    #pragma unroll
    for (int j = 0; j < 8; j++) {
        const int col = h * NDH + j * 8 + (lane & 3) * 2;
        {
            float a0 = o[j][0] * inv0, a1 = o[j][1] * inv0;
            __nv_bfloat16 h0 = __float2bfloat16_rn(a0);
            __nv_bfloat16 h1 = __float2bfloat16_rn(a1);
            size_t off = (size_t)(b * NS + q0 + qloc0) * ND + col;
            *(__nv_bfloat162*)&g_Chi[off] = __nv_bfloat162(h0, h1);
            *(__nv_bfloat162*)&g_Clo[off] = __nv_bfloat162(
                __float2bfloat16_rn(a0 - __bfloat162float(h0)),
                __float2bfloat16_rn(a1 - __bfloat162float(h1)));
        }
        {
            float a0 = o[j][2] * inv1, a1 = o[j][3] * inv1;
            __nv_bfloat16 h0 = __float2bfloat16_rn(a0);
            __nv_bfloat16 h1 = __float2bfloat16_rn(a1);
            size_t off = (size_t)(b * NS + q0 + qloc1) * ND + col;
            *(__nv_bfloat162*)&g_Chi[off] = __nv_bfloat162(h0, h1);
            *(__nv_bfloat162*)&g_Clo[off] = __nv_bfloat162(
                __float2bfloat16_rn(a0 - __bfloat162float(h0)),
                __float2bfloat16_rn(a1 - __bfloat162float(h1)));
        }
    }
}

// ---------------- launch ----------------
extern "C" void kernel_launch(void* const* d_in, const int* in_sizes, int n_in,
                              void* d_out, int out_size) {
    const float* key      = (const float*)d_in[0];
    const float* value    = (const float*)d_in[1];
    const float* query    = (const float*)d_in[2];
    const float* Wq       = (const float*)d_in[3];
    const float* bq       = (const float*)d_in[4];
    const float* Wk       = (const float*)d_in[5];
    const float* bk       = (const float*)d_in[6];
    const float* Wv       = (const float*)d_in[7];
    const float* bv       = (const float*)d_in[8];
    const float* Wo       = (const float*)d_in[9];
    const float* bo       = (const float*)d_in[10];
    const float* rel_bias = (const float*)d_in[11];
    const void*  mask     = (const void*)d_in[12];
    float* out = (float*)d_out;

    cudaFuncSetAttribute(attn_kernel, cudaFuncAttributeMaxDynamicSharedMemorySize, AT_TOTAL);
    cudaFuncSetAttribute(mma_qkv_kernel, cudaFuncAttributeMaxDynamicSharedMemorySize, PJ_SMEM);
    cudaFuncSetAttribute(mma_out_kernel, cudaFuncAttributeMaxDynamicSharedMemorySize, PJ_SMEM);

    detect_mask_kernel<<<1, 1024>>>(mask);
    maskprep_kernel<<<(NB * NS * NS / 32) / 256, 256>>>(mask);
    biastab_kernel<<<(NH * 4096) / 256, 256>>>(rel_bias);
    convert_x_kernel<<<3 * XSZ / 4 / 256, 256>>>(query, key, value);
    convert_w_kernel<<<dim3(16, 16, 4), dim3(32, 8)>>>(Wq, Wk, Wv, Wo);

    dim3 pgrid(ND / 128, (NB * NS) / 128, 3);
    mma_qkv_kernel<<<pgrid, 256, PJ_SMEM>>>(bq, bk, bv);

    dim3 agrid(NS / 128, NH, NB);
    attn_kernel<<<agrid, 256, AT_TOTAL>>>();

    dim3 ogrid(ND / 128, (NB * NS) / 128);
    mma_out_kernel<<<ogrid, 256, PJ_SMEM>>>(bo, out);
}